// round 8
// baseline (speedup 1.0000x reference)
#include <cuda_runtime.h>
#include <cuda_bf16.h>
#include <math.h>
#include <stdint.h>

#define BB 4
#define SS 2048
#define DD 1024
#define HH 16
#define HDD 64
#define M_TOT (BB*SS)          // 8192
#define N_QKV (3*DD)           // 3072

// ---------------- device scratch (allocation-free) ----------------
__device__ __nv_bfloat16 g_qkv_hi[(size_t)M_TOT * N_QKV];
__device__ __nv_bfloat16 g_qkv_lo[(size_t)M_TOT * N_QKV];
__device__ __nv_bfloat16 g_x_hi[(size_t)M_TOT * DD];
__device__ __nv_bfloat16 g_x_lo[(size_t)M_TOT * DD];
__device__ __nv_bfloat16 g_wa_hi[(size_t)DD * N_QKV];
__device__ __nv_bfloat16 g_wa_lo[(size_t)DD * N_QKV];
__device__ __nv_bfloat16 g_wp_hi[(size_t)DD * DD];
__device__ __nv_bfloat16 g_wp_lo[(size_t)DD * DD];
__device__ __nv_bfloat16 g_y_hi[(size_t)M_TOT * DD];
__device__ __nv_bfloat16 g_y_lo[(size_t)M_TOT * DD];

// ---------------- small PTX helpers ----------------
__device__ __forceinline__ void cp16(uint32_t dst, const void* src) {
    asm volatile("cp.async.cg.shared.global [%0], [%1], 16;" :: "r"(dst), "l"(src));
}
#define CP_COMMIT() asm volatile("cp.async.commit_group;")
#define CP_WAIT0()  asm volatile("cp.async.wait_group 0;")
#define CP_WAIT2()  asm volatile("cp.async.wait_group 2;")

__device__ __forceinline__ void ldsm_x4(uint32_t addr,
    uint32_t& r0, uint32_t& r1, uint32_t& r2, uint32_t& r3) {
    asm volatile("ldmatrix.sync.aligned.m8n8.x4.shared.b16 {%0,%1,%2,%3}, [%4];"
        : "=r"(r0), "=r"(r1), "=r"(r2), "=r"(r3) : "r"(addr));
}
__device__ __forceinline__ void ldsm_x4_t(uint32_t addr,
    uint32_t& r0, uint32_t& r1, uint32_t& r2, uint32_t& r3) {
    asm volatile("ldmatrix.sync.aligned.m8n8.x4.trans.shared.b16 {%0,%1,%2,%3}, [%4];"
        : "=r"(r0), "=r"(r1), "=r"(r2), "=r"(r3) : "r"(addr));
}
__device__ __forceinline__ void mma_bf16(float* d,
    uint32_t a0, uint32_t a1, uint32_t a2, uint32_t a3,
    uint32_t b0, uint32_t b1)
{
    asm volatile(
        "mma.sync.aligned.m16n8k16.row.col.f32.bf16.bf16.f32 "
        "{%0,%1,%2,%3}, {%4,%5,%6,%7}, {%8,%9}, {%0,%1,%2,%3};\n"
        : "+f"(d[0]), "+f"(d[1]), "+f"(d[2]), "+f"(d[3])
        : "r"(a0), "r"(a1), "r"(a2), "r"(a3), "r"(b0), "r"(b1));
}
__device__ __forceinline__ void pack_split(float x, float y, uint32_t& hi, uint32_t& lo) {
    __nv_bfloat162 h = __floats2bfloat162_rn(x, y);
    hi = *(uint32_t*)&h;
    float rx = x - __bfloat162float(h.x);
    float ry = y - __bfloat162float(h.y);
    __nv_bfloat162 l = __floats2bfloat162_rn(rx, ry);
    lo = *(uint32_t*)&l;
}

// ---------------- split pass: fp32 -> (bf16 hi, bf16 lo) ----------------
__global__ void __launch_bounds__(256) split_kernel(
    const float* __restrict__ in,
    __nv_bfloat16* __restrict__ hi, __nv_bfloat16* __restrict__ lo, int n4)
{
    int i = blockIdx.x * blockDim.x + threadIdx.x;
    if (i >= n4) return;
    float4 v = ((const float4*)in)[i];
    uint32_t h0, l0, h1, l1;
    pack_split(v.x, v.y, h0, l0);
    pack_split(v.z, v.w, h1, l1);
    ((uint32_t*)hi)[2*i]   = h0;
    ((uint32_t*)hi)[2*i+1] = h1;
    ((uint32_t*)lo)[2*i]   = l0;
    ((uint32_t*)lo)[2*i+1] = l1;
}

// ---------------------------------------------------------------------------
// mma.sync split-bf16 GEMM: C[M,N] = (Ahi+Alo) @ (Whi+Wlo) + bias
// CTA tile 256x128, BK=32, 8 warps (4x2), warp tile 64x64 -> 4x8 m16n8k16.
// 3-stage cp.async pipeline. MMA:LDSM ratio 6:1.
// smem/stage (bf16 elems): Ah[256][40], Al[256][40], Bh[32][136], Bl[32][136]
// ---------------------------------------------------------------------------
#define A_STR 40
#define B_STR 136
#define A_HI_OFF 0
#define A_LO_OFF (256*A_STR)                     // 10240
#define B_HI_OFF (2*256*A_STR)                   // 20480
#define B_LO_OFF (2*256*A_STR + 32*B_STR)        // 24832
#define STAGE_ELEMS (2*256*A_STR + 2*32*B_STR)   // 29184 elems
#define STAGE_BYTES (STAGE_ELEMS * 2)            // 58368 B
#define GEMM_SMEM (3 * STAGE_BYTES)              // 175104 B

template<int SPLIT_OUT>
__global__ void __launch_bounds__(256, 1) gemm_bias_tc(
    const __nv_bfloat16* __restrict__ Ahi, const __nv_bfloat16* __restrict__ Alo,
    const __nv_bfloat16* __restrict__ Whi, const __nv_bfloat16* __restrict__ Wlo,
    const float* __restrict__ bias, float* __restrict__ C,
    __nv_bfloat16* __restrict__ Chi, __nv_bfloat16* __restrict__ Clo,
    int M, int N, int K)
{
    extern __shared__ __nv_bfloat16 smem[];
    const uint32_t smem_u32 = (uint32_t)__cvta_generic_to_shared(smem);

    const int tid  = threadIdx.x;
    const int lane = tid & 31;
    const int warp = tid >> 5;
    const int wm   = warp >> 1;          // 0..3 (64 rows each)
    const int wn   = warp & 1;           // 0..1 (64 cols each)
    const int bm   = blockIdx.y * 256;
    const int bn   = blockIdx.x * 128;

    // global-load mapping: A: thread t loads full row t (4x16B) of hi and lo;
    // B: thread t loads 16B chunk (t&7) of k-row (t>>3) for hi and lo.
    const int arow = tid;                // 0..255
    const int bkr  = tid >> 3;           // 0..31
    const int bcol = (tid & 7) * 16;     // 0..112

    const __nv_bfloat16* ah_g = Ahi + (size_t)(bm + arow) * K;
    const __nv_bfloat16* al_g = Alo + (size_t)(bm + arow) * K;
    const __nv_bfloat16* bh_g = Whi + (size_t)bkr * N + bn + bcol;
    const __nv_bfloat16* bl_g = Wlo + (size_t)bkr * N + bn + bcol;

    const uint32_t a_sm = smem_u32 + (arow * A_STR) * 2;
    const uint32_t b_sm = smem_u32 + (bkr * B_STR + bcol) * 2;

    auto issue_stage = [&](int k0, int s) {
        const uint32_t so = (uint32_t)(s * STAGE_BYTES);
        #pragma unroll
        for (int c = 0; c < 4; c++) {
            cp16(so + a_sm + A_HI_OFF*2 + c*16, ah_g + k0 + c*8);
            cp16(so + a_sm + A_LO_OFF*2 + c*16, al_g + k0 + c*8);
        }
        cp16(so + b_sm + B_HI_OFF*2,      bh_g + (size_t)k0 * N);
        cp16(so + b_sm + B_HI_OFF*2 + 16, bh_g + (size_t)k0 * N + 8);
        cp16(so + b_sm + B_LO_OFF*2,      bl_g + (size_t)k0 * N);
        cp16(so + b_sm + B_LO_OFF*2 + 16, bl_g + (size_t)k0 * N + 8);
        CP_COMMIT();
    };

    float acc[4][8][4];
    #pragma unroll
    for (int mt = 0; mt < 4; mt++)
        #pragma unroll
        for (int nt = 0; nt < 8; nt++)
            #pragma unroll
            for (int r = 0; r < 4; r++) acc[mt][nt][r] = 0.0f;

    // ldmatrix lane addressing (element indices)
    const int a_row_in = (lane & 7) + ((lane >> 3) & 1) * 8;
    const int a_kcol   = (lane >> 4) * 8;
    const int b_krow   = ((lane >> 3) & 1) * 8 + (lane & 7);
    const int b_ncol   = (lane >> 4) * 8;

    const int NST = K / 32;   // 32
    issue_stage(0, 0);
    issue_stage(32, 1);
    issue_stage(64, 2);

    for (int t = 0; t < NST; t++) {
        const int s = t % 3;
        CP_WAIT2();
        __syncthreads();

        const uint32_t so = (uint32_t)(s * STAGE_BYTES);
        const uint32_t ah_base = smem_u32 + so + A_HI_OFF * 2;
        const uint32_t al_base = smem_u32 + so + A_LO_OFF * 2;
        const uint32_t bh_base = smem_u32 + so + B_HI_OFF * 2;
        const uint32_t bl_base = smem_u32 + so + B_LO_OFF * 2;

        #pragma unroll
        for (int kk = 0; kk < 32; kk += 16) {
            uint32_t bh[8][2], bl[8][2];
            #pragma unroll
            for (int p = 0; p < 4; p++) {
                const uint32_t baddr = (uint32_t)(((kk + b_krow) * B_STR +
                                       wn * 64 + p * 16 + b_ncol) * 2);
                ldsm_x4_t(bh_base + baddr, bh[2*p][0], bh[2*p][1], bh[2*p+1][0], bh[2*p+1][1]);
                ldsm_x4_t(bl_base + baddr, bl[2*p][0], bl[2*p][1], bl[2*p+1][0], bl[2*p+1][1]);
            }
            #pragma unroll
            for (int mt = 0; mt < 4; mt++) {
                const uint32_t aaddr = (uint32_t)(((wm * 64 + mt * 16 + a_row_in) * A_STR +
                                       kk + a_kcol) * 2);
                uint32_t ah0, ah1, ah2, ah3, al0, al1, al2, al3;
                ldsm_x4(ah_base + aaddr, ah0, ah1, ah2, ah3);
                ldsm_x4(al_base + aaddr, al0, al1, al2, al3);
                #pragma unroll
                for (int nt = 0; nt < 8; nt++)
                    mma_bf16(acc[mt][nt], ah0, ah1, ah2, ah3, bh[nt][0], bh[nt][1]);
                #pragma unroll
                for (int nt = 0; nt < 8; nt++)
                    mma_bf16(acc[mt][nt], ah0, ah1, ah2, ah3, bl[nt][0], bl[nt][1]);
                #pragma unroll
                for (int nt = 0; nt < 8; nt++)
                    mma_bf16(acc[mt][nt], al0, al1, al2, al3, bh[nt][0], bh[nt][1]);
            }
        }
        __syncthreads();
        if (t + 3 < NST) issue_stage((t + 3) * 32, s);
    }

    // ---- epilogue: add bias, write out ----
    #pragma unroll
    for (int mt = 0; mt < 4; mt++) {
        int r = bm + wm * 64 + mt * 16 + (lane >> 2);
        #pragma unroll
        for (int nt = 0; nt < 8; nt++) {
            int cidx = bn + wn * 64 + nt * 8 + (lane & 3) * 2;
            float2 bv = *(const float2*)&bias[cidx];
            float o0 = acc[mt][nt][0] + bv.x;
            float o1 = acc[mt][nt][1] + bv.y;
            float o2 = acc[mt][nt][2] + bv.x;
            float o3 = acc[mt][nt][3] + bv.y;
            if (SPLIT_OUT) {
                uint32_t h0, l0, h1, l1;
                pack_split(o0, o1, h0, l0);
                pack_split(o2, o3, h1, l1);
                *(uint32_t*)&Chi[(size_t)r * N + cidx]       = h0;
                *(uint32_t*)&Clo[(size_t)r * N + cidx]       = l0;
                *(uint32_t*)&Chi[(size_t)(r + 8) * N + cidx] = h1;
                *(uint32_t*)&Clo[(size_t)(r + 8) * N + cidx] = l1;
            } else {
                float2 w0 = { o0, o1 }, w1 = { o2, o3 };
                *(float2*)&C[(size_t)r * N + cidx]       = w0;
                *(float2*)&C[(size_t)(r + 8) * N + cidx] = w1;
            }
        }
    }
}

// ---------------------------------------------------------------------------
// Tensor-core causal flash attention (round-5 known-good).
// ---------------------------------------------------------------------------
#define ASTR 72
#define QH_OFF 0
#define QL_OFF (128*ASTR)
#define KH_OFF (2*128*ASTR)
#define KL_OFF (2*128*ASTR + 64*ASTR)
#define VH_OFF (2*128*ASTR + 2*64*ASTR)
#define VL_OFF (2*128*ASTR + 3*64*ASTR)
#define ATT_SMEM_ELEMS (2*128*ASTR + 4*64*ASTR)
#define ATT_SMEM_BYTES (ATT_SMEM_ELEMS * 2)

__global__ void __launch_bounds__(256, 2) flash_attn_tc(
    const __nv_bfloat16* __restrict__ qkvh, const __nv_bfloat16* __restrict__ qkvl,
    __nv_bfloat16* __restrict__ yh, __nv_bfloat16* __restrict__ yl)
{
    extern __shared__ __nv_bfloat16 sm_att[];
    const uint32_t smb = (uint32_t)__cvta_generic_to_shared(sm_att);

    const int qb = blockIdx.x;
    const int h  = blockIdx.y;
    const int b  = blockIdx.z;
    const int tid  = threadIdx.x;
    const int lane = tid & 31;
    const int warp = tid >> 5;
    const int m0   = warp * 16;
    const int q0   = qb * 128;
    const float scale = 0.125f;

    {
        const int row  = tid >> 1;
        const int colb = (tid & 1) * 32;
        const size_t base = ((size_t)(b * SS + q0 + row)) * N_QKV + h * HDD + colb;
        const uint32_t dh = smb + (QH_OFF + row * ASTR + colb) * 2;
        const uint32_t dl = smb + (QL_OFF + row * ASTR + colb) * 2;
        #pragma unroll
        for (int c = 0; c < 4; c++) {
            cp16(dh + c * 16, qkvh + base + c * 8);
            cp16(dl + c * 16, qkvl + base + c * 8);
        }
        CP_COMMIT();
    }

    float o[8][4];
    float s[8][4];
    float mrow[2] = { -1e30f, -1e30f };
    float lrow[2] = { 0.0f, 0.0f };
    #pragma unroll
    for (int i = 0; i < 8; i++)
        #pragma unroll
        for (int j = 0; j < 4; j++) o[i][j] = 0.0f;

    const int a_row = (lane & 7) + ((lane >> 3) & 1) * 8;
    const int a_k   = (lane >> 4) * 8;
    const int kb_n  = (lane & 7) + ((lane >> 4) & 1) * 8;
    const int kb_k  = ((lane >> 3) & 1) * 8;
    const int vb_k  = ((lane >> 3) & 1) * 8 + (lane & 7);
    const int vb_n  = (lane >> 4) * 8;

    const int r_in  = lane >> 2;
    const int c_in  = (lane & 3) * 2;

    const int kmax = 2 * qb + 1;

    for (int kb = 0; kb <= kmax; kb++) {
        __syncthreads();
        {
            const int row  = tid >> 2;
            const int colb = (tid & 3) * 16;
            const size_t base = ((size_t)(b * SS + kb * 64 + row)) * N_QKV + h * HDD + colb;
            const uint32_t dkh = smb + (KH_OFF + row * ASTR + colb) * 2;
            const uint32_t dkl = smb + (KL_OFF + row * ASTR + colb) * 2;
            const uint32_t dvh = smb + (VH_OFF + row * ASTR + colb) * 2;
            const uint32_t dvl = smb + (VL_OFF + row * ASTR + colb) * 2;
            #pragma unroll
            for (int c = 0; c < 2; c++) {
                cp16(dkh + c * 16, qkvh + base + DD     + c * 8);
                cp16(dkl + c * 16, qkvl + base + DD     + c * 8);
                cp16(dvh + c * 16, qkvh + base + 2 * DD + c * 8);
                cp16(dvl + c * 16, qkvl + base + 2 * DD + c * 8);
            }
            CP_COMMIT();
        }
        CP_WAIT0();
        __syncthreads();

        #pragma unroll
        for (int i = 0; i < 8; i++)
            #pragma unroll
            for (int j = 0; j < 4; j++) s[i][j] = 0.0f;

        #pragma unroll
        for (int kk = 0; kk < 64; kk += 16) {
            uint32_t qh0, qh1, qh2, qh3, ql0, ql1, ql2, ql3;
            const uint32_t qaddr = (uint32_t)(((m0 + a_row) * ASTR + kk + a_k) * 2);
            ldsm_x4(smb + QH_OFF * 2 + qaddr, qh0, qh1, qh2, qh3);
            ldsm_x4(smb + QL_OFF * 2 + qaddr, ql0, ql1, ql2, ql3);
            #pragma unroll
            for (int np = 0; np < 4; np++) {
                uint32_t kh0, kh1, kh2, kh3, kl0, kl1, kl2, kl3;
                const uint32_t kaddr = (uint32_t)(((np * 16 + kb_n) * ASTR + kk + kb_k) * 2);
                ldsm_x4(smb + KH_OFF * 2 + kaddr, kh0, kh1, kh2, kh3);
                ldsm_x4(smb + KL_OFF * 2 + kaddr, kl0, kl1, kl2, kl3);
                mma_bf16(s[2*np],   qh0, qh1, qh2, qh3, kh0, kh1);
                mma_bf16(s[2*np],   qh0, qh1, qh2, qh3, kl0, kl1);
                mma_bf16(s[2*np],   ql0, ql1, ql2, ql3, kh0, kh1);
                mma_bf16(s[2*np+1], qh0, qh1, qh2, qh3, kh2, kh3);
                mma_bf16(s[2*np+1], qh0, qh1, qh2, qh3, kl2, kl3);
                mma_bf16(s[2*np+1], ql0, ql1, ql2, ql3, kh2, kh3);
            }
        }

        const bool masked = (kb >= 2 * qb);
        float alpha[2];
        #pragma unroll
        for (int r = 0; r < 2; r++) {
            const int rowg = q0 + m0 + r_in + 8 * r;
            float mx = -1e30f;
            #pragma unroll
            for (int nt = 0; nt < 8; nt++) {
                #pragma unroll
                for (int c = 0; c < 2; c++) {
                    float t = s[nt][2*r + c] * scale;
                    if (masked) {
                        int keyg = kb * 64 + nt * 8 + c_in + c;
                        if (keyg > rowg) t = -1e30f;
                    }
                    s[nt][2*r + c] = t;
                    mx = fmaxf(mx, t);
                }
            }
            mx = fmaxf(mx, __shfl_xor_sync(0xffffffffu, mx, 1));
            mx = fmaxf(mx, __shfl_xor_sync(0xffffffffu, mx, 2));
            float mnew = fmaxf(mrow[r], mx);
            alpha[r] = __expf(mrow[r] - mnew);
            mrow[r] = mnew;
            float ps = 0.0f;
            #pragma unroll
            for (int nt = 0; nt < 8; nt++) {
                #pragma unroll
                for (int c = 0; c < 2; c++) {
                    float p = __expf(s[nt][2*r + c] - mnew);
                    s[nt][2*r + c] = p;
                    ps += p;
                }
            }
            lrow[r] = lrow[r] * alpha[r] + ps;
        }
        #pragma unroll
        for (int nh = 0; nh < 8; nh++) {
            o[nh][0] *= alpha[0]; o[nh][1] *= alpha[0];
            o[nh][2] *= alpha[1]; o[nh][3] *= alpha[1];
        }

        #pragma unroll
        for (int kt = 0; kt < 4; kt++) {
            uint32_t ph[4], pl[4];
            pack_split(s[2*kt][0],   s[2*kt][1],   ph[0], pl[0]);
            pack_split(s[2*kt][2],   s[2*kt][3],   ph[1], pl[1]);
            pack_split(s[2*kt+1][0], s[2*kt+1][1], ph[2], pl[2]);
            pack_split(s[2*kt+1][2], s[2*kt+1][3], ph[3], pl[3]);
            #pragma unroll
            for (int np = 0; np < 4; np++) {
                uint32_t vh0, vh1, vh2, vh3, vl0, vl1, vl2, vl3;
                const uint32_t vaddr = (uint32_t)(((kt * 16 + vb_k) * ASTR + np * 16 + vb_n) * 2);
                ldsm_x4_t(smb + VH_OFF * 2 + vaddr, vh0, vh1, vh2, vh3);
                ldsm_x4_t(smb + VL_OFF * 2 + vaddr, vl0, vl1, vl2, vl3);
                mma_bf16(o[2*np],   ph[0], ph[1], ph[2], ph[3], vh0, vh1);
                mma_bf16(o[2*np],   ph[0], ph[1], ph[2], ph[3], vl0, vl1);
                mma_bf16(o[2*np],   pl[0], pl[1], pl[2], pl[3], vh0, vh1);
                mma_bf16(o[2*np+1], ph[0], ph[1], ph[2], ph[3], vh2, vh3);
                mma_bf16(o[2*np+1], ph[0], ph[1], ph[2], ph[3], vl2, vl3);
                mma_bf16(o[2*np+1], pl[0], pl[1], pl[2], pl[3], vh2, vh3);
            }
        }
    }

    float inv[2];
    #pragma unroll
    for (int r = 0; r < 2; r++) {
        lrow[r] += __shfl_xor_sync(0xffffffffu, lrow[r], 1);
        lrow[r] += __shfl_xor_sync(0xffffffffu, lrow[r], 2);
        inv[r] = 1.0f / lrow[r];
    }
    #pragma unroll
    for (int nh = 0; nh < 8; nh++) {
        #pragma unroll
        for (int r = 0; r < 2; r++) {
            float a0 = o[nh][2*r]     * inv[r];
            float a1 = o[nh][2*r + 1] * inv[r];
            uint32_t hi, lo;
            pack_split(a0, a1, hi, lo);
            const size_t row = (size_t)(b * SS + q0 + m0 + r_in + 8 * r);
            const int col = h * HDD + nh * 8 + c_in;
            *(uint32_t*)&yh[row * DD + col] = hi;
            *(uint32_t*)&yl[row * DD + col] = lo;
        }
    }
}

// ---------------------------------------------------------------------------
extern "C" void kernel_launch(void* const* d_in, const int* in_sizes, int n_in,
                              void* d_out, int out_size)
{
    const float* x      = (const float*)d_in[0];
    const float* W_attn = (const float*)d_in[1];
    const float* b_attn = (const float*)d_in[2];
    const float* W_proj = (const float*)d_in[3];
    const float* b_proj = (const float*)d_in[4];
    float* out = (float*)d_out;

    __nv_bfloat16 *qkv_hi, *qkv_lo, *x_hi, *x_lo, *wa_hi, *wa_lo, *wp_hi, *wp_lo, *y_hi, *y_lo;
    cudaGetSymbolAddress((void**)&qkv_hi, g_qkv_hi);
    cudaGetSymbolAddress((void**)&qkv_lo, g_qkv_lo);
    cudaGetSymbolAddress((void**)&x_hi,  g_x_hi);
    cudaGetSymbolAddress((void**)&x_lo,  g_x_lo);
    cudaGetSymbolAddress((void**)&wa_hi, g_wa_hi);
    cudaGetSymbolAddress((void**)&wa_lo, g_wa_lo);
    cudaGetSymbolAddress((void**)&wp_hi, g_wp_hi);
    cudaGetSymbolAddress((void**)&wp_lo, g_wp_lo);
    cudaGetSymbolAddress((void**)&y_hi,  g_y_hi);
    cudaGetSymbolAddress((void**)&y_lo,  g_y_lo);

    cudaFuncSetAttribute(gemm_bias_tc<0>,
                         cudaFuncAttributeMaxDynamicSharedMemorySize, GEMM_SMEM);
    cudaFuncSetAttribute(gemm_bias_tc<1>,
                         cudaFuncAttributeMaxDynamicSharedMemorySize, GEMM_SMEM);
    cudaFuncSetAttribute(flash_attn_tc,
                         cudaFuncAttributeMaxDynamicSharedMemorySize, ATT_SMEM_BYTES);

    // 0) split fp32 inputs into bf16 hi/lo
    {
        int n4 = (M_TOT * DD) / 4;
        split_kernel<<<(n4 + 255) / 256, 256>>>(x, x_hi, x_lo, n4);
        n4 = (DD * N_QKV) / 4;
        split_kernel<<<(n4 + 255) / 256, 256>>>(W_attn, wa_hi, wa_lo, n4);
        n4 = (DD * DD) / 4;
        split_kernel<<<(n4 + 255) / 256, 256>>>(W_proj, wp_hi, wp_lo, n4);
    }

    // 1) QKV projection -> qkv hi/lo (bf16 split written directly)
    {
        dim3 grid(N_QKV / 128, M_TOT / 256);
        gemm_bias_tc<1><<<grid, 256, GEMM_SMEM>>>(
            x_hi, x_lo, wa_hi, wa_lo, b_attn, nullptr, qkv_hi, qkv_lo,
            M_TOT, N_QKV, DD);
    }

    // 2) tensor-core causal flash attention -> y hi/lo
    {
        dim3 grid(SS / 128, HH, BB);
        flash_attn_tc<<<grid, 256, ATT_SMEM_BYTES>>>(qkv_hi, qkv_lo, y_hi, y_lo);
    }

    // 3) output projection -> fp32 out
    {
        dim3 grid(DD / 128, M_TOT / 256);
        gemm_bias_tc<0><<<grid, 256, GEMM_SMEM>>>(
            y_hi, y_lo, wp_hi, wp_lo, b_proj, out, nullptr, nullptr,
            M_TOT, DD, DD);
    }
}

// round 10
// speedup vs baseline: 1.1950x; 1.1950x over previous
#include <cuda_runtime.h>
#include <cuda_bf16.h>
#include <math.h>
#include <stdint.h>

#define BB 4
#define SS 2048
#define DD 1024
#define HH 16
#define HDD 64
#define M_TOT (BB*SS)          // 8192
#define N_QKV (3*DD)           // 3072

// ---------------- device scratch (allocation-free) ----------------
__device__ __nv_bfloat16 g_qkv_hi[(size_t)M_TOT * N_QKV];
__device__ __nv_bfloat16 g_qkv_lo[(size_t)M_TOT * N_QKV];
__device__ __nv_bfloat16 g_x_hi[(size_t)M_TOT * DD];
__device__ __nv_bfloat16 g_x_lo[(size_t)M_TOT * DD];
__device__ __nv_bfloat16 g_wa_hi[(size_t)DD * N_QKV];
__device__ __nv_bfloat16 g_wa_lo[(size_t)DD * N_QKV];
__device__ __nv_bfloat16 g_wp_hi[(size_t)DD * DD];
__device__ __nv_bfloat16 g_wp_lo[(size_t)DD * DD];
__device__ __nv_bfloat16 g_y_hi[(size_t)M_TOT * DD];
__device__ __nv_bfloat16 g_y_lo[(size_t)M_TOT * DD];

// ---------------- small PTX helpers ----------------
__device__ __forceinline__ void cp16(uint32_t dst, const void* src) {
    asm volatile("cp.async.cg.shared.global [%0], [%1], 16;" :: "r"(dst), "l"(src));
}
#define CP_COMMIT() asm volatile("cp.async.commit_group;")
#define CP_WAIT0()  asm volatile("cp.async.wait_group 0;")
#define CP_WAIT1()  asm volatile("cp.async.wait_group 1;")
#define CP_WAIT2()  asm volatile("cp.async.wait_group 2;")

__device__ __forceinline__ void ldsm_x4(uint32_t addr,
    uint32_t& r0, uint32_t& r1, uint32_t& r2, uint32_t& r3) {
    asm volatile("ldmatrix.sync.aligned.m8n8.x4.shared.b16 {%0,%1,%2,%3}, [%4];"
        : "=r"(r0), "=r"(r1), "=r"(r2), "=r"(r3) : "r"(addr));
}
__device__ __forceinline__ void ldsm_x4_t(uint32_t addr,
    uint32_t& r0, uint32_t& r1, uint32_t& r2, uint32_t& r3) {
    asm volatile("ldmatrix.sync.aligned.m8n8.x4.trans.shared.b16 {%0,%1,%2,%3}, [%4];"
        : "=r"(r0), "=r"(r1), "=r"(r2), "=r"(r3) : "r"(addr));
}
__device__ __forceinline__ void mma_bf16(float* d,
    uint32_t a0, uint32_t a1, uint32_t a2, uint32_t a3,
    uint32_t b0, uint32_t b1)
{
    asm volatile(
        "mma.sync.aligned.m16n8k16.row.col.f32.bf16.bf16.f32 "
        "{%0,%1,%2,%3}, {%4,%5,%6,%7}, {%8,%9}, {%0,%1,%2,%3};\n"
        : "+f"(d[0]), "+f"(d[1]), "+f"(d[2]), "+f"(d[3])
        : "r"(a0), "r"(a1), "r"(a2), "r"(a3), "r"(b0), "r"(b1));
}
__device__ __forceinline__ void pack_split(float x, float y, uint32_t& hi, uint32_t& lo) {
    __nv_bfloat162 h = __floats2bfloat162_rn(x, y);
    hi = *(uint32_t*)&h;
    float rx = x - __bfloat162float(h.x);
    float ry = y - __bfloat162float(h.y);
    __nv_bfloat162 l = __floats2bfloat162_rn(rx, ry);
    lo = *(uint32_t*)&l;
}

// ---------------- split pass: fp32 -> (bf16 hi, bf16 lo) ----------------
__global__ void __launch_bounds__(256) split_kernel(
    const float* __restrict__ in,
    __nv_bfloat16* __restrict__ hi, __nv_bfloat16* __restrict__ lo, int n4)
{
    int i = blockIdx.x * blockDim.x + threadIdx.x;
    if (i >= n4) return;
    float4 v = ((const float4*)in)[i];
    uint32_t h0, l0, h1, l1;
    pack_split(v.x, v.y, h0, l0);
    pack_split(v.z, v.w, h1, l1);
    ((uint32_t*)hi)[2*i]   = h0;
    ((uint32_t*)hi)[2*i+1] = h1;
    ((uint32_t*)lo)[2*i]   = l0;
    ((uint32_t*)lo)[2*i+1] = l1;
}

// ---------------------------------------------------------------------------
// mma.sync split-bf16 GEMM: C = (Ahi+Alo)@(Whi+Wlo) + bias
// 128x128 CTA tile, BK=32, 8 warps (2x4), warp tile 64x32.
// 3-stage cp.async pipeline, ONE __syncthreads per k-iteration.
// ---------------------------------------------------------------------------
#define A_STR 40
#define B_STR 136
#define A_HI_OFF 0
#define A_LO_OFF (128*A_STR)
#define B_HI_OFF (2*128*A_STR)
#define B_LO_OFF (2*128*A_STR + 32*B_STR)
#define STAGE_ELEMS (2*128*A_STR + 2*32*B_STR)   // 18944 elems
#define STAGE_BYTES (STAGE_ELEMS * 2)            // 37888 B
#define GEMM_SMEM (3 * STAGE_BYTES)              // 113664 B

template<int SPLIT_OUT>
__global__ void __launch_bounds__(256, 2) gemm_bias_tc(
    const __nv_bfloat16* __restrict__ Ahi, const __nv_bfloat16* __restrict__ Alo,
    const __nv_bfloat16* __restrict__ Whi, const __nv_bfloat16* __restrict__ Wlo,
    const float* __restrict__ bias, float* __restrict__ C,
    __nv_bfloat16* __restrict__ Chi, __nv_bfloat16* __restrict__ Clo,
    int M, int N, int K)
{
    extern __shared__ __nv_bfloat16 smem[];
    const uint32_t smem_u32 = (uint32_t)__cvta_generic_to_shared(smem);

    const int tid  = threadIdx.x;
    const int lane = tid & 31;
    const int warp = tid >> 5;
    const int wm   = warp >> 2;          // 0..1
    const int wn   = warp & 3;           // 0..3
    const int bm   = blockIdx.y * 128;
    const int bn   = blockIdx.x * 128;

    const int ar = tid >> 1;
    const int aj = (tid & 1) * 16;
    const int kr = tid >> 3;
    const int bj = (tid & 7) * 16;

    const __nv_bfloat16* ah_g = Ahi + (size_t)(bm + ar) * K + aj;
    const __nv_bfloat16* al_g = Alo + (size_t)(bm + ar) * K + aj;
    const __nv_bfloat16* bh_g = Whi + (size_t)kr * N + bn + bj;
    const __nv_bfloat16* bl_g = Wlo + (size_t)kr * N + bn + bj;

    const uint32_t a_sm = smem_u32 + (ar * A_STR + aj) * 2;
    const uint32_t b_sm = smem_u32 + (kr * B_STR + bj) * 2;

    auto issue_stage = [&](int k0, int s) {
        const uint32_t so = (uint32_t)(s * STAGE_BYTES);
        cp16(so + a_sm + A_HI_OFF*2,      ah_g + k0);
        cp16(so + a_sm + A_HI_OFF*2 + 16, ah_g + k0 + 8);
        cp16(so + a_sm + A_LO_OFF*2,      al_g + k0);
        cp16(so + a_sm + A_LO_OFF*2 + 16, al_g + k0 + 8);
        cp16(so + b_sm + B_HI_OFF*2,      bh_g + (size_t)k0 * N);
        cp16(so + b_sm + B_HI_OFF*2 + 16, bh_g + (size_t)k0 * N + 8);
        cp16(so + b_sm + B_LO_OFF*2,      bl_g + (size_t)k0 * N);
        cp16(so + b_sm + B_LO_OFF*2 + 16, bl_g + (size_t)k0 * N + 8);
        CP_COMMIT();
    };

    float acc[4][4][4];
    #pragma unroll
    for (int mt = 0; mt < 4; mt++)
        #pragma unroll
        for (int nt = 0; nt < 4; nt++)
            #pragma unroll
            for (int r = 0; r < 4; r++) acc[mt][nt][r] = 0.0f;

    const int a_row_in = (lane & 7) + ((lane >> 3) & 1) * 8;
    const int a_kcol   = (lane >> 4) * 8;
    const int b_krow   = ((lane >> 3) & 1) * 8 + (lane & 7);
    const int b_ncol   = (lane >> 4) * 8;

    const int NST = K / 32;   // 32
    issue_stage(0, 0);
    issue_stage(32, 1);
    issue_stage(64, 2);

    for (int t = 0; t < NST; t++) {
        // wait for stage t (groups retire in order; tail adjusts the count)
        if (t + 2 < NST)      { CP_WAIT2(); }
        else if (t + 1 < NST) { CP_WAIT1(); }
        else                  { CP_WAIT0(); }
        __syncthreads();
        // refill slot consumed at t-1 (safe: all warps passed the barrier)
        if (t >= 1 && t + 2 < NST) issue_stage((t + 2) * 32, (t + 2) % 3);

        const uint32_t so = (uint32_t)((t % 3) * STAGE_BYTES);
        const uint32_t ah_base = smem_u32 + so + A_HI_OFF * 2;
        const uint32_t al_base = smem_u32 + so + A_LO_OFF * 2;
        const uint32_t bh_base = smem_u32 + so + B_HI_OFF * 2;
        const uint32_t bl_base = smem_u32 + so + B_LO_OFF * 2;

        #pragma unroll
        for (int kk = 0; kk < 32; kk += 16) {
            uint32_t bh[4][2], bl[4][2];
            #pragma unroll
            for (int p = 0; p < 2; p++) {
                const uint32_t baddr = (uint32_t)(((kk + b_krow) * B_STR +
                                       wn * 32 + p * 16 + b_ncol) * 2);
                ldsm_x4_t(bh_base + baddr, bh[2*p][0], bh[2*p][1], bh[2*p+1][0], bh[2*p+1][1]);
                ldsm_x4_t(bl_base + baddr, bl[2*p][0], bl[2*p][1], bl[2*p+1][0], bl[2*p+1][1]);
            }
            #pragma unroll
            for (int mt = 0; mt < 4; mt++) {
                const uint32_t aaddr = (uint32_t)(((wm * 64 + mt * 16 + a_row_in) * A_STR +
                                       kk + a_kcol) * 2);
                uint32_t ah0, ah1, ah2, ah3, al0, al1, al2, al3;
                ldsm_x4(ah_base + aaddr, ah0, ah1, ah2, ah3);
                ldsm_x4(al_base + aaddr, al0, al1, al2, al3);
                #pragma unroll
                for (int nt = 0; nt < 4; nt++)
                    mma_bf16(acc[mt][nt], ah0, ah1, ah2, ah3, bh[nt][0], bh[nt][1]);
                #pragma unroll
                for (int nt = 0; nt < 4; nt++)
                    mma_bf16(acc[mt][nt], ah0, ah1, ah2, ah3, bl[nt][0], bl[nt][1]);
                #pragma unroll
                for (int nt = 0; nt < 4; nt++)
                    mma_bf16(acc[mt][nt], al0, al1, al2, al3, bh[nt][0], bh[nt][1]);
            }
        }
        // no trailing barrier: next iteration's top barrier orders slot reuse
    }

    // ---- epilogue: add bias, write out ----
    #pragma unroll
    for (int mt = 0; mt < 4; mt++) {
        int r = bm + wm * 64 + mt * 16 + (lane >> 2);
        #pragma unroll
        for (int nt = 0; nt < 4; nt++) {
            int cidx = bn + wn * 32 + nt * 8 + (lane & 3) * 2;
            float2 bv = *(const float2*)&bias[cidx];
            float o0 = acc[mt][nt][0] + bv.x;
            float o1 = acc[mt][nt][1] + bv.y;
            float o2 = acc[mt][nt][2] + bv.x;
            float o3 = acc[mt][nt][3] + bv.y;
            if (SPLIT_OUT) {
                uint32_t h0, l0, h1, l1;
                pack_split(o0, o1, h0, l0);
                pack_split(o2, o3, h1, l1);
                *(uint32_t*)&Chi[(size_t)r * N + cidx]       = h0;
                *(uint32_t*)&Clo[(size_t)r * N + cidx]       = l0;
                *(uint32_t*)&Chi[(size_t)(r + 8) * N + cidx] = h1;
                *(uint32_t*)&Clo[(size_t)(r + 8) * N + cidx] = l1;
            } else {
                float2 w0 = { o0, o1 }, w1 = { o2, o3 };
                *(float2*)&C[(size_t)r * N + cidx]       = w0;
                *(float2*)&C[(size_t)(r + 8) * N + cidx] = w1;
            }
        }
    }
}

// ---------------------------------------------------------------------------
// Tensor-core causal flash attention, double-buffered K/V.
// Grid (S/128, H, B), 256 threads (8 warps x m16).
// smem elems (stride 72): Q hi/lo 2*128*72 = 18432; KV slots 2 x 18432
//   slot layout: KH +0, KL +4608, VH +9216, VL +13824
// ---------------------------------------------------------------------------
#define ASTR 72
#define QH_OFF 0
#define QL_OFF (128*ASTR)                 // 9216
#define KV_BASE (2*128*ASTR)              // 18432
#define KV_SLOT (4*64*ASTR)               // 18432
#define KH_O 0
#define KL_O (64*ASTR)                    // 4608
#define VH_O (2*64*ASTR)                  // 9216
#define VL_O (3*64*ASTR)                  // 13824
#define ATT_SMEM_ELEMS (KV_BASE + 2*KV_SLOT)   // 55296
#define ATT_SMEM_BYTES (ATT_SMEM_ELEMS * 2)    // 110592

__global__ void __launch_bounds__(256, 2) flash_attn_tc(
    const __nv_bfloat16* __restrict__ qkvh, const __nv_bfloat16* __restrict__ qkvl,
    __nv_bfloat16* __restrict__ yh, __nv_bfloat16* __restrict__ yl)
{
    extern __shared__ __nv_bfloat16 sm_att[];
    const uint32_t smb = (uint32_t)__cvta_generic_to_shared(sm_att);

    const int qb = blockIdx.x;
    const int h  = blockIdx.y;
    const int b  = blockIdx.z;
    const int tid  = threadIdx.x;
    const int lane = tid & 31;
    const int warp = tid >> 5;
    const int m0   = warp * 16;
    const int q0   = qb * 128;
    const float scale = 0.125f;

    // KV load mapping (shared by prologue + steady state)
    const int kv_row  = tid >> 2;
    const int kv_colb = (tid & 3) * 16;

    auto load_kv = [&](int kb, int slot) {
        const size_t base = ((size_t)(b * SS + kb * 64 + kv_row)) * N_QKV + h * HDD + kv_colb;
        const uint32_t sb = smb + (KV_BASE + slot * KV_SLOT) * 2;
        const uint32_t dkh = sb + (KH_O + kv_row * ASTR + kv_colb) * 2;
        const uint32_t dkl = sb + (KL_O + kv_row * ASTR + kv_colb) * 2;
        const uint32_t dvh = sb + (VH_O + kv_row * ASTR + kv_colb) * 2;
        const uint32_t dvl = sb + (VL_O + kv_row * ASTR + kv_colb) * 2;
        #pragma unroll
        for (int c = 0; c < 2; c++) {
            cp16(dkh + c * 16, qkvh + base + DD     + c * 8);
            cp16(dkl + c * 16, qkvl + base + DD     + c * 8);
            cp16(dvh + c * 16, qkvh + base + 2 * DD + c * 8);
            cp16(dvl + c * 16, qkvl + base + 2 * DD + c * 8);
        }
        CP_COMMIT();
    };

    // ---- prologue: Q (group), KV(0) (group) ----
    {
        const int row  = tid >> 1;
        const int colb = (tid & 1) * 32;
        const size_t base = ((size_t)(b * SS + q0 + row)) * N_QKV + h * HDD + colb;
        const uint32_t dh = smb + (QH_OFF + row * ASTR + colb) * 2;
        const uint32_t dl = smb + (QL_OFF + row * ASTR + colb) * 2;
        #pragma unroll
        for (int c = 0; c < 4; c++) {
            cp16(dh + c * 16, qkvh + base + c * 8);
            cp16(dl + c * 16, qkvl + base + c * 8);
        }
        CP_COMMIT();
    }
    load_kv(0, 0);

    float o[8][4];
    float s[8][4];
    float mrow[2] = { -1e30f, -1e30f };
    float lrow[2] = { 0.0f, 0.0f };
    #pragma unroll
    for (int i = 0; i < 8; i++)
        #pragma unroll
        for (int j = 0; j < 4; j++) o[i][j] = 0.0f;

    const int a_row = (lane & 7) + ((lane >> 3) & 1) * 8;
    const int a_k   = (lane >> 4) * 8;
    const int kb_n  = (lane & 7) + ((lane >> 4) & 1) * 8;
    const int kb_k  = ((lane >> 3) & 1) * 8;
    const int vb_k  = ((lane >> 3) & 1) * 8 + (lane & 7);
    const int vb_n  = (lane >> 4) * 8;

    const int r_in  = lane >> 2;
    const int c_in  = (lane & 3) * 2;

    const int kmax = 2 * qb + 1;

    for (int kb = 0; kb <= kmax; kb++) {
        CP_WAIT0();          // Q + KV(kb) resident (only KV(kb) pending in steady state)
        __syncthreads();     // all warps done with the other slot
        if (kb + 1 <= kmax) load_kv(kb + 1, (kb + 1) & 1);   // prefetch into freed slot

        const uint32_t kvb = smb + (KV_BASE + (kb & 1) * KV_SLOT) * 2;

        #pragma unroll
        for (int i = 0; i < 8; i++)
            #pragma unroll
            for (int j = 0; j < 4; j++) s[i][j] = 0.0f;

        #pragma unroll
        for (int kk = 0; kk < 64; kk += 16) {
            uint32_t qh0, qh1, qh2, qh3, ql0, ql1, ql2, ql3;
            const uint32_t qaddr = (uint32_t)(((m0 + a_row) * ASTR + kk + a_k) * 2);
            ldsm_x4(smb + QH_OFF * 2 + qaddr, qh0, qh1, qh2, qh3);
            ldsm_x4(smb + QL_OFF * 2 + qaddr, ql0, ql1, ql2, ql3);
            #pragma unroll
            for (int np = 0; np < 4; np++) {
                uint32_t kh0, kh1, kh2, kh3, kl0, kl1, kl2, kl3;
                const uint32_t kaddr = (uint32_t)(((np * 16 + kb_n) * ASTR + kk + kb_k) * 2);
                ldsm_x4(kvb + KH_O * 2 + kaddr, kh0, kh1, kh2, kh3);
                ldsm_x4(kvb + KL_O * 2 + kaddr, kl0, kl1, kl2, kl3);
                mma_bf16(s[2*np],   qh0, qh1, qh2, qh3, kh0, kh1);
                mma_bf16(s[2*np],   qh0, qh1, qh2, qh3, kl0, kl1);
                mma_bf16(s[2*np],   ql0, ql1, ql2, ql3, kh0, kh1);
                mma_bf16(s[2*np+1], qh0, qh1, qh2, qh3, kh2, kh3);
                mma_bf16(s[2*np+1], qh0, qh1, qh2, qh3, kl2, kl3);
                mma_bf16(s[2*np+1], ql0, ql1, ql2, ql3, kh2, kh3);
            }
        }

        const bool masked = (kb >= 2 * qb);
        float alpha[2];
        #pragma unroll
        for (int r = 0; r < 2; r++) {
            const int rowg = q0 + m0 + r_in + 8 * r;
            float mx = -1e30f;
            #pragma unroll
            for (int nt = 0; nt < 8; nt++) {
                #pragma unroll
                for (int c = 0; c < 2; c++) {
                    float t = s[nt][2*r + c] * scale;
                    if (masked) {
                        int keyg = kb * 64 + nt * 8 + c_in + c;
                        if (keyg > rowg) t = -1e30f;
                    }
                    s[nt][2*r + c] = t;
                    mx = fmaxf(mx, t);
                }
            }
            mx = fmaxf(mx, __shfl_xor_sync(0xffffffffu, mx, 1));
            mx = fmaxf(mx, __shfl_xor_sync(0xffffffffu, mx, 2));
            float mnew = fmaxf(mrow[r], mx);
            alpha[r] = __expf(mrow[r] - mnew);
            mrow[r] = mnew;
            float ps = 0.0f;
            #pragma unroll
            for (int nt = 0; nt < 8; nt++) {
                #pragma unroll
                for (int c = 0; c < 2; c++) {
                    float p = __expf(s[nt][2*r + c] - mnew);
                    s[nt][2*r + c] = p;
                    ps += p;
                }
            }
            lrow[r] = lrow[r] * alpha[r] + ps;
        }
        #pragma unroll
        for (int nh = 0; nh < 8; nh++) {
            o[nh][0] *= alpha[0]; o[nh][1] *= alpha[0];
            o[nh][2] *= alpha[1]; o[nh][3] *= alpha[1];
        }

        #pragma unroll
        for (int kt = 0; kt < 4; kt++) {
            uint32_t ph[4], pl[4];
            pack_split(s[2*kt][0],   s[2*kt][1],   ph[0], pl[0]);
            pack_split(s[2*kt][2],   s[2*kt][3],   ph[1], pl[1]);
            pack_split(s[2*kt+1][0], s[2*kt+1][1], ph[2], pl[2]);
            pack_split(s[2*kt+1][2], s[2*kt+1][3], ph[3], pl[3]);
            #pragma unroll
            for (int np = 0; np < 4; np++) {
                uint32_t vh0, vh1, vh2, vh3, vl0, vl1, vl2, vl3;
                const uint32_t vaddr = (uint32_t)(((kt * 16 + vb_k) * ASTR + np * 16 + vb_n) * 2);
                ldsm_x4_t(kvb + VH_O * 2 + vaddr, vh0, vh1, vh2, vh3);
                ldsm_x4_t(kvb + VL_O * 2 + vaddr, vl0, vl1, vl2, vl3);
                mma_bf16(o[2*np],   ph[0], ph[1], ph[2], ph[3], vh0, vh1);
                mma_bf16(o[2*np],   ph[0], ph[1], ph[2], ph[3], vl0, vl1);
                mma_bf16(o[2*np],   pl[0], pl[1], pl[2], pl[3], vh0, vh1);
                mma_bf16(o[2*np+1], ph[0], ph[1], ph[2], ph[3], vh2, vh3);
                mma_bf16(o[2*np+1], ph[0], ph[1], ph[2], ph[3], vl2, vl3);
                mma_bf16(o[2*np+1], pl[0], pl[1], pl[2], pl[3], vh2, vh3);
            }
        }
    }

    float inv[2];
    #pragma unroll
    for (int r = 0; r < 2; r++) {
        lrow[r] += __shfl_xor_sync(0xffffffffu, lrow[r], 1);
        lrow[r] += __shfl_xor_sync(0xffffffffu, lrow[r], 2);
        inv[r] = 1.0f / lrow[r];
    }
    #pragma unroll
    for (int nh = 0; nh < 8; nh++) {
        #pragma unroll
        for (int r = 0; r < 2; r++) {
            float a0 = o[nh][2*r]     * inv[r];
            float a1 = o[nh][2*r + 1] * inv[r];
            uint32_t hi, lo;
            pack_split(a0, a1, hi, lo);
            const size_t row = (size_t)(b * SS + q0 + m0 + r_in + 8 * r);
            const int col = h * HDD + nh * 8 + c_in;
            *(uint32_t*)&yh[row * DD + col] = hi;
            *(uint32_t*)&yl[row * DD + col] = lo;
        }
    }
}

// ---------------------------------------------------------------------------
extern "C" void kernel_launch(void* const* d_in, const int* in_sizes, int n_in,
                              void* d_out, int out_size)
{
    const float* x      = (const float*)d_in[0];
    const float* W_attn = (const float*)d_in[1];
    const float* b_attn = (const float*)d_in[2];
    const float* W_proj = (const float*)d_in[3];
    const float* b_proj = (const float*)d_in[4];
    float* out = (float*)d_out;

    __nv_bfloat16 *qkv_hi, *qkv_lo, *x_hi, *x_lo, *wa_hi, *wa_lo, *wp_hi, *wp_lo, *y_hi, *y_lo;
    cudaGetSymbolAddress((void**)&qkv_hi, g_qkv_hi);
    cudaGetSymbolAddress((void**)&qkv_lo, g_qkv_lo);
    cudaGetSymbolAddress((void**)&x_hi,  g_x_hi);
    cudaGetSymbolAddress((void**)&x_lo,  g_x_lo);
    cudaGetSymbolAddress((void**)&wa_hi, g_wa_hi);
    cudaGetSymbolAddress((void**)&wa_lo, g_wa_lo);
    cudaGetSymbolAddress((void**)&wp_hi, g_wp_hi);
    cudaGetSymbolAddress((void**)&wp_lo, g_wp_lo);
    cudaGetSymbolAddress((void**)&y_hi,  g_y_hi);
    cudaGetSymbolAddress((void**)&y_lo,  g_y_lo);

    cudaFuncSetAttribute(gemm_bias_tc<0>,
                         cudaFuncAttributeMaxDynamicSharedMemorySize, GEMM_SMEM);
    cudaFuncSetAttribute(gemm_bias_tc<1>,
                         cudaFuncAttributeMaxDynamicSharedMemorySize, GEMM_SMEM);
    cudaFuncSetAttribute(flash_attn_tc,
                         cudaFuncAttributeMaxDynamicSharedMemorySize, ATT_SMEM_BYTES);

    // 0) split fp32 inputs into bf16 hi/lo
    {
        int n4 = (M_TOT * DD) / 4;
        split_kernel<<<(n4 + 255) / 256, 256>>>(x, x_hi, x_lo, n4);
        n4 = (DD * N_QKV) / 4;
        split_kernel<<<(n4 + 255) / 256, 256>>>(W_attn, wa_hi, wa_lo, n4);
        n4 = (DD * DD) / 4;
        split_kernel<<<(n4 + 255) / 256, 256>>>(W_proj, wp_hi, wp_lo, n4);
    }

    // 1) QKV projection -> qkv hi/lo
    {
        dim3 grid(N_QKV / 128, M_TOT / 128);
        gemm_bias_tc<1><<<grid, 256, GEMM_SMEM>>>(
            x_hi, x_lo, wa_hi, wa_lo, b_attn, nullptr, qkv_hi, qkv_lo,
            M_TOT, N_QKV, DD);
    }

    // 2) tensor-core causal flash attention -> y hi/lo
    {
        dim3 grid(SS / 128, HH, BB);
        flash_attn_tc<<<grid, 256, ATT_SMEM_BYTES>>>(qkv_hi, qkv_lo, y_hi, y_lo);
    }

    // 3) output projection -> fp32 out
    {
        dim3 grid(DD / 128, M_TOT / 128);
        gemm_bias_tc<0><<<grid, 256, GEMM_SMEM>>>(
            y_hi, y_lo, wp_hi, wp_lo, b_proj, out, nullptr, nullptr,
            M_TOT, DD, DD);
    }
}

// round 11
// speedup vs baseline: 1.5930x; 1.3330x over previous
#include <cuda_runtime.h>
#include <cuda_fp16.h>
#include <math.h>
#include <stdint.h>

#define BB 4
#define SS 2048
#define DD 1024
#define HH 16
#define HDD 64
#define M_TOT (BB*SS)          // 8192
#define N_QKV (3*DD)           // 3072

// ---------------- device scratch (allocation-free) ----------------
__device__ __half g_qkv_hi[(size_t)M_TOT * N_QKV];
__device__ __half g_qkv_lo[(size_t)M_TOT * N_QKV];
__device__ __half g_x_hi[(size_t)M_TOT * DD];
__device__ __half g_wa_hi[(size_t)DD * N_QKV];
__device__ __half g_wa_lo[(size_t)DD * N_QKV];
__device__ __half g_wp_hi[(size_t)DD * DD];
__device__ __half g_wp_lo[(size_t)DD * DD];
__device__ __half g_y_hi[(size_t)M_TOT * DD];

// ---------------- small PTX helpers ----------------
__device__ __forceinline__ void cp16(uint32_t dst, const void* src) {
    asm volatile("cp.async.cg.shared.global [%0], [%1], 16;" :: "r"(dst), "l"(src));
}
#define CP_COMMIT() asm volatile("cp.async.commit_group;")
#define CP_WAIT0()  asm volatile("cp.async.wait_group 0;")
#define CP_WAIT1()  asm volatile("cp.async.wait_group 1;")
#define CP_WAIT2()  asm volatile("cp.async.wait_group 2;")

__device__ __forceinline__ void ldsm_x4(uint32_t addr,
    uint32_t& r0, uint32_t& r1, uint32_t& r2, uint32_t& r3) {
    asm volatile("ldmatrix.sync.aligned.m8n8.x4.shared.b16 {%0,%1,%2,%3}, [%4];"
        : "=r"(r0), "=r"(r1), "=r"(r2), "=r"(r3) : "r"(addr));
}
__device__ __forceinline__ void ldsm_x4_t(uint32_t addr,
    uint32_t& r0, uint32_t& r1, uint32_t& r2, uint32_t& r3) {
    asm volatile("ldmatrix.sync.aligned.m8n8.x4.trans.shared.b16 {%0,%1,%2,%3}, [%4];"
        : "=r"(r0), "=r"(r1), "=r"(r2), "=r"(r3) : "r"(addr));
}
__device__ __forceinline__ void mma_f16(float* d,
    uint32_t a0, uint32_t a1, uint32_t a2, uint32_t a3,
    uint32_t b0, uint32_t b1)
{
    asm volatile(
        "mma.sync.aligned.m16n8k16.row.col.f32.f16.f16.f32 "
        "{%0,%1,%2,%3}, {%4,%5,%6,%7}, {%8,%9}, {%0,%1,%2,%3};\n"
        : "+f"(d[0]), "+f"(d[1]), "+f"(d[2]), "+f"(d[3])
        : "r"(a0), "r"(a1), "r"(a2), "r"(a3), "r"(b0), "r"(b1));
}
__device__ __forceinline__ void pack_split_h(float x, float y, uint32_t& hi, uint32_t& lo) {
    __half2 h = __floats2half2_rn(x, y);
    hi = *(uint32_t*)&h;
    float rx = x - __half2float(h.x);
    float ry = y - __half2float(h.y);
    __half2 l = __floats2half2_rn(rx, ry);
    lo = *(uint32_t*)&l;
}
__device__ __forceinline__ uint32_t pack_h(float x, float y) {
    __half2 h = __floats2half2_rn(x, y);
    return *(uint32_t*)&h;
}

// ---------------- split passes ----------------
__global__ void __launch_bounds__(256) split_hilo_kernel(
    const float* __restrict__ in,
    __half* __restrict__ hi, __half* __restrict__ lo, int n4)
{
    int i = blockIdx.x * blockDim.x + threadIdx.x;
    if (i >= n4) return;
    float4 v = ((const float4*)in)[i];
    uint32_t h0, l0, h1, l1;
    pack_split_h(v.x, v.y, h0, l0);
    pack_split_h(v.z, v.w, h1, l1);
    ((uint32_t*)hi)[2*i]   = h0;
    ((uint32_t*)hi)[2*i+1] = h1;
    ((uint32_t*)lo)[2*i]   = l0;
    ((uint32_t*)lo)[2*i+1] = l1;
}
__global__ void __launch_bounds__(256) split_hi_kernel(
    const float* __restrict__ in, __half* __restrict__ hi, int n4)
{
    int i = blockIdx.x * blockDim.x + threadIdx.x;
    if (i >= n4) return;
    float4 v = ((const float4*)in)[i];
    ((uint32_t*)hi)[2*i]   = pack_h(v.x, v.y);
    ((uint32_t*)hi)[2*i+1] = pack_h(v.z, v.w);
}

// ---------------------------------------------------------------------------
// mma.sync fp16 2-product GEMM: C = Ah @ (Whi+Wlo) + bias
// 128x128 CTA tile, BK=32, 8 warps (2x4), warp tile 64x32.
// 3-stage cp.async pipeline, one __syncthreads per k-iteration.
// smem/stage (half elems): Ah[128][40], Bh[32][136], Bl[32][136]
// ---------------------------------------------------------------------------
#define A_STR 40
#define B_STR 136
#define A_HI_OFF 0
#define B_HI_OFF (128*A_STR)                   // 5120
#define B_LO_OFF (128*A_STR + 32*B_STR)        // 9472
#define STAGE_ELEMS (128*A_STR + 2*32*B_STR)   // 13824 elems
#define STAGE_BYTES (STAGE_ELEMS * 2)          // 27648 B
#define GEMM_SMEM (3 * STAGE_BYTES)            // 82944 B

template<int SPLIT_OUT>
__global__ void __launch_bounds__(256, 2) gemm_bias_tc(
    const __half* __restrict__ Ahi,
    const __half* __restrict__ Whi, const __half* __restrict__ Wlo,
    const float* __restrict__ bias, float* __restrict__ C,
    __half* __restrict__ Chi, __half* __restrict__ Clo,
    int M, int N, int K)
{
    extern __shared__ __half smem[];
    const uint32_t smem_u32 = (uint32_t)__cvta_generic_to_shared(smem);

    const int tid  = threadIdx.x;
    const int lane = tid & 31;
    const int warp = tid >> 5;
    const int wm   = warp >> 2;          // 0..1
    const int wn   = warp & 3;           // 0..3
    const int bm   = blockIdx.y * 128;
    const int bn   = blockIdx.x * 128;

    const int ar = tid >> 1;
    const int aj = (tid & 1) * 16;
    const int kr = tid >> 3;
    const int bj = (tid & 7) * 16;

    const __half* ah_g = Ahi + (size_t)(bm + ar) * K + aj;
    const __half* bh_g = Whi + (size_t)kr * N + bn + bj;
    const __half* bl_g = Wlo + (size_t)kr * N + bn + bj;

    const uint32_t a_sm = smem_u32 + (ar * A_STR + aj) * 2;
    const uint32_t b_sm = smem_u32 + (kr * B_STR + bj) * 2;

    auto issue_stage = [&](int k0, int s) {
        const uint32_t so = (uint32_t)(s * STAGE_BYTES);
        cp16(so + a_sm + A_HI_OFF*2,      ah_g + k0);
        cp16(so + a_sm + A_HI_OFF*2 + 16, ah_g + k0 + 8);
        cp16(so + b_sm + B_HI_OFF*2,      bh_g + (size_t)k0 * N);
        cp16(so + b_sm + B_HI_OFF*2 + 16, bh_g + (size_t)k0 * N + 8);
        cp16(so + b_sm + B_LO_OFF*2,      bl_g + (size_t)k0 * N);
        cp16(so + b_sm + B_LO_OFF*2 + 16, bl_g + (size_t)k0 * N + 8);
        CP_COMMIT();
    };

    float acc[4][4][4];
    #pragma unroll
    for (int mt = 0; mt < 4; mt++)
        #pragma unroll
        for (int nt = 0; nt < 4; nt++)
            #pragma unroll
            for (int r = 0; r < 4; r++) acc[mt][nt][r] = 0.0f;

    const int a_row_in = (lane & 7) + ((lane >> 3) & 1) * 8;
    const int a_kcol   = (lane >> 4) * 8;
    const int b_krow   = ((lane >> 3) & 1) * 8 + (lane & 7);
    const int b_ncol   = (lane >> 4) * 8;

    const int NST = K / 32;   // 32
    issue_stage(0, 0);
    issue_stage(32, 1);
    issue_stage(64, 2);

    for (int t = 0; t < NST; t++) {
        if (t + 2 < NST)      { CP_WAIT2(); }
        else if (t + 1 < NST) { CP_WAIT1(); }
        else                  { CP_WAIT0(); }
        __syncthreads();
        if (t >= 1 && t + 2 < NST) issue_stage((t + 2) * 32, (t + 2) % 3);

        const uint32_t so = (uint32_t)((t % 3) * STAGE_BYTES);
        const uint32_t ah_base = smem_u32 + so + A_HI_OFF * 2;
        const uint32_t bh_base = smem_u32 + so + B_HI_OFF * 2;
        const uint32_t bl_base = smem_u32 + so + B_LO_OFF * 2;

        #pragma unroll
        for (int kk = 0; kk < 32; kk += 16) {
            uint32_t bh[4][2], bl[4][2];
            #pragma unroll
            for (int p = 0; p < 2; p++) {
                const uint32_t baddr = (uint32_t)(((kk + b_krow) * B_STR +
                                       wn * 32 + p * 16 + b_ncol) * 2);
                ldsm_x4_t(bh_base + baddr, bh[2*p][0], bh[2*p][1], bh[2*p+1][0], bh[2*p+1][1]);
                ldsm_x4_t(bl_base + baddr, bl[2*p][0], bl[2*p][1], bl[2*p+1][0], bl[2*p+1][1]);
            }
            #pragma unroll
            for (int mt = 0; mt < 4; mt++) {
                const uint32_t aaddr = (uint32_t)(((wm * 64 + mt * 16 + a_row_in) * A_STR +
                                       kk + a_kcol) * 2);
                uint32_t ah0, ah1, ah2, ah3;
                ldsm_x4(ah_base + aaddr, ah0, ah1, ah2, ah3);
                #pragma unroll
                for (int nt = 0; nt < 4; nt++)
                    mma_f16(acc[mt][nt], ah0, ah1, ah2, ah3, bh[nt][0], bh[nt][1]);
                #pragma unroll
                for (int nt = 0; nt < 4; nt++)
                    mma_f16(acc[mt][nt], ah0, ah1, ah2, ah3, bl[nt][0], bl[nt][1]);
            }
        }
    }

    // ---- epilogue: add bias, write out ----
    #pragma unroll
    for (int mt = 0; mt < 4; mt++) {
        int r = bm + wm * 64 + mt * 16 + (lane >> 2);
        #pragma unroll
        for (int nt = 0; nt < 4; nt++) {
            int cidx = bn + wn * 32 + nt * 8 + (lane & 3) * 2;
            float2 bv = *(const float2*)&bias[cidx];
            float o0 = acc[mt][nt][0] + bv.x;
            float o1 = acc[mt][nt][1] + bv.y;
            float o2 = acc[mt][nt][2] + bv.x;
            float o3 = acc[mt][nt][3] + bv.y;
            if (SPLIT_OUT) {
                uint32_t h0, l0, h1, l1;
                pack_split_h(o0, o1, h0, l0);
                pack_split_h(o2, o3, h1, l1);
                *(uint32_t*)&Chi[(size_t)r * N + cidx]       = h0;
                *(uint32_t*)&Clo[(size_t)r * N + cidx]       = l0;
                *(uint32_t*)&Chi[(size_t)(r + 8) * N + cidx] = h1;
                *(uint32_t*)&Clo[(size_t)(r + 8) * N + cidx] = l1;
            } else {
                float2 w0 = { o0, o1 }, w1 = { o2, o3 };
                *(float2*)&C[(size_t)r * N + cidx]       = w0;
                *(float2*)&C[(size_t)(r + 8) * N + cidx] = w1;
            }
        }
    }
}

// ---------------------------------------------------------------------------
// fp16 tensor-core causal flash attention, double-buffered K/V.
// S = 3-product (softmax-sensitive); PV = 2-product (Ph*Vh + Ph*Vl).
// Grid (S/128, H, B) with qb reversed for heavy-first scheduling.
// ---------------------------------------------------------------------------
#define ASTR 72
#define QH_OFF 0
#define QL_OFF (128*ASTR)                 // 9216
#define KV_BASE (2*128*ASTR)              // 18432
#define KV_SLOT (4*64*ASTR)               // 18432
#define KH_O 0
#define KL_O (64*ASTR)
#define VH_O (2*64*ASTR)
#define VL_O (3*64*ASTR)
#define ATT_SMEM_ELEMS (KV_BASE + 2*KV_SLOT)   // 55296
#define ATT_SMEM_BYTES (ATT_SMEM_ELEMS * 2)    // 110592

__global__ void __launch_bounds__(256, 2) flash_attn_tc(
    const __half* __restrict__ qkvh, const __half* __restrict__ qkvl,
    __half* __restrict__ yh)
{
    extern __shared__ __half sm_att[];
    const uint32_t smb = (uint32_t)__cvta_generic_to_shared(sm_att);

    const int qb = (gridDim.x - 1) - blockIdx.x;   // heavy blocks first
    const int h  = blockIdx.y;
    const int b  = blockIdx.z;
    const int tid  = threadIdx.x;
    const int lane = tid & 31;
    const int warp = tid >> 5;
    const int m0   = warp * 16;
    const int q0   = qb * 128;
    const float scale = 0.125f;

    const int kv_row  = tid >> 2;
    const int kv_colb = (tid & 3) * 16;

    auto load_kv = [&](int kb, int slot) {
        const size_t base = ((size_t)(b * SS + kb * 64 + kv_row)) * N_QKV + h * HDD + kv_colb;
        const uint32_t sb = smb + (KV_BASE + slot * KV_SLOT) * 2;
        const uint32_t dkh = sb + (KH_O + kv_row * ASTR + kv_colb) * 2;
        const uint32_t dkl = sb + (KL_O + kv_row * ASTR + kv_colb) * 2;
        const uint32_t dvh = sb + (VH_O + kv_row * ASTR + kv_colb) * 2;
        const uint32_t dvl = sb + (VL_O + kv_row * ASTR + kv_colb) * 2;
        #pragma unroll
        for (int c = 0; c < 2; c++) {
            cp16(dkh + c * 16, qkvh + base + DD     + c * 8);
            cp16(dkl + c * 16, qkvl + base + DD     + c * 8);
            cp16(dvh + c * 16, qkvh + base + 2 * DD + c * 8);
            cp16(dvl + c * 16, qkvl + base + 2 * DD + c * 8);
        }
        CP_COMMIT();
    };

    // ---- prologue: Q (hi/lo), KV(0) ----
    {
        const int row  = tid >> 1;
        const int colb = (tid & 1) * 32;
        const size_t base = ((size_t)(b * SS + q0 + row)) * N_QKV + h * HDD + colb;
        const uint32_t dh = smb + (QH_OFF + row * ASTR + colb) * 2;
        const uint32_t dl = smb + (QL_OFF + row * ASTR + colb) * 2;
        #pragma unroll
        for (int c = 0; c < 4; c++) {
            cp16(dh + c * 16, qkvh + base + c * 8);
            cp16(dl + c * 16, qkvl + base + c * 8);
        }
        CP_COMMIT();
    }
    load_kv(0, 0);

    float o[8][4];
    float s[8][4];
    float mrow[2] = { -1e30f, -1e30f };
    float lrow[2] = { 0.0f, 0.0f };
    #pragma unroll
    for (int i = 0; i < 8; i++)
        #pragma unroll
        for (int j = 0; j < 4; j++) o[i][j] = 0.0f;

    const int a_row = (lane & 7) + ((lane >> 3) & 1) * 8;
    const int a_k   = (lane >> 4) * 8;
    const int kb_n  = (lane & 7) + ((lane >> 4) & 1) * 8;
    const int kb_k  = ((lane >> 3) & 1) * 8;
    const int vb_k  = ((lane >> 3) & 1) * 8 + (lane & 7);
    const int vb_n  = (lane >> 4) * 8;

    const int r_in  = lane >> 2;
    const int c_in  = (lane & 3) * 2;

    const int kmax = 2 * qb + 1;

    for (int kb = 0; kb <= kmax; kb++) {
        CP_WAIT0();
        __syncthreads();
        if (kb + 1 <= kmax) load_kv(kb + 1, (kb + 1) & 1);

        const uint32_t kvb = smb + (KV_BASE + (kb & 1) * KV_SLOT) * 2;

        #pragma unroll
        for (int i = 0; i < 8; i++)
            #pragma unroll
            for (int j = 0; j < 4; j++) s[i][j] = 0.0f;

        // ---- S = Q K^T, 3-product fp16 ----
        #pragma unroll
        for (int kk = 0; kk < 64; kk += 16) {
            uint32_t qh0, qh1, qh2, qh3, ql0, ql1, ql2, ql3;
            const uint32_t qaddr = (uint32_t)(((m0 + a_row) * ASTR + kk + a_k) * 2);
            ldsm_x4(smb + QH_OFF * 2 + qaddr, qh0, qh1, qh2, qh3);
            ldsm_x4(smb + QL_OFF * 2 + qaddr, ql0, ql1, ql2, ql3);
            #pragma unroll
            for (int np = 0; np < 4; np++) {
                uint32_t kh0, kh1, kh2, kh3, kl0, kl1, kl2, kl3;
                const uint32_t kaddr = (uint32_t)(((np * 16 + kb_n) * ASTR + kk + kb_k) * 2);
                ldsm_x4(kvb + KH_O * 2 + kaddr, kh0, kh1, kh2, kh3);
                ldsm_x4(kvb + KL_O * 2 + kaddr, kl0, kl1, kl2, kl3);
                mma_f16(s[2*np],   qh0, qh1, qh2, qh3, kh0, kh1);
                mma_f16(s[2*np],   qh0, qh1, qh2, qh3, kl0, kl1);
                mma_f16(s[2*np],   ql0, ql1, ql2, ql3, kh0, kh1);
                mma_f16(s[2*np+1], qh0, qh1, qh2, qh3, kh2, kh3);
                mma_f16(s[2*np+1], qh0, qh1, qh2, qh3, kl2, kl3);
                mma_f16(s[2*np+1], ql0, ql1, ql2, ql3, kh2, kh3);
            }
        }

        const bool masked = (kb >= 2 * qb);
        float alpha[2];
        #pragma unroll
        for (int r = 0; r < 2; r++) {
            const int rowg = q0 + m0 + r_in + 8 * r;
            float mx = -1e30f;
            #pragma unroll
            for (int nt = 0; nt < 8; nt++) {
                #pragma unroll
                for (int c = 0; c < 2; c++) {
                    float t = s[nt][2*r + c] * scale;
                    if (masked) {
                        int keyg = kb * 64 + nt * 8 + c_in + c;
                        if (keyg > rowg) t = -1e30f;
                    }
                    s[nt][2*r + c] = t;
                    mx = fmaxf(mx, t);
                }
            }
            mx = fmaxf(mx, __shfl_xor_sync(0xffffffffu, mx, 1));
            mx = fmaxf(mx, __shfl_xor_sync(0xffffffffu, mx, 2));
            float mnew = fmaxf(mrow[r], mx);
            alpha[r] = __expf(mrow[r] - mnew);
            mrow[r] = mnew;
            float ps = 0.0f;
            #pragma unroll
            for (int nt = 0; nt < 8; nt++) {
                #pragma unroll
                for (int c = 0; c < 2; c++) {
                    float p = __expf(s[nt][2*r + c] - mnew);
                    s[nt][2*r + c] = p;
                    ps += p;
                }
            }
            lrow[r] = lrow[r] * alpha[r] + ps;
        }
        #pragma unroll
        for (int nh = 0; nh < 8; nh++) {
            o[nh][0] *= alpha[0]; o[nh][1] *= alpha[0];
            o[nh][2] *= alpha[1]; o[nh][3] *= alpha[1];
        }

        // ---- O += P V, 2-product fp16 (P hi only) ----
        #pragma unroll
        for (int kt = 0; kt < 4; kt++) {
            uint32_t ph[4];
            ph[0] = pack_h(s[2*kt][0],   s[2*kt][1]);
            ph[1] = pack_h(s[2*kt][2],   s[2*kt][3]);
            ph[2] = pack_h(s[2*kt+1][0], s[2*kt+1][1]);
            ph[3] = pack_h(s[2*kt+1][2], s[2*kt+1][3]);
            #pragma unroll
            for (int np = 0; np < 4; np++) {
                uint32_t vh0, vh1, vh2, vh3, vl0, vl1, vl2, vl3;
                const uint32_t vaddr = (uint32_t)(((kt * 16 + vb_k) * ASTR + np * 16 + vb_n) * 2);
                ldsm_x4_t(kvb + VH_O * 2 + vaddr, vh0, vh1, vh2, vh3);
                ldsm_x4_t(kvb + VL_O * 2 + vaddr, vl0, vl1, vl2, vl3);
                mma_f16(o[2*np],   ph[0], ph[1], ph[2], ph[3], vh0, vh1);
                mma_f16(o[2*np],   ph[0], ph[1], ph[2], ph[3], vl0, vl1);
                mma_f16(o[2*np+1], ph[0], ph[1], ph[2], ph[3], vh2, vh3);
                mma_f16(o[2*np+1], ph[0], ph[1], ph[2], ph[3], vl2, vl3);
            }
        }
    }

    float inv[2];
    #pragma unroll
    for (int r = 0; r < 2; r++) {
        lrow[r] += __shfl_xor_sync(0xffffffffu, lrow[r], 1);
        lrow[r] += __shfl_xor_sync(0xffffffffu, lrow[r], 2);
        inv[r] = 1.0f / lrow[r];
    }
    #pragma unroll
    for (int nh = 0; nh < 8; nh++) {
        #pragma unroll
        for (int r = 0; r < 2; r++) {
            float a0 = o[nh][2*r]     * inv[r];
            float a1 = o[nh][2*r + 1] * inv[r];
            const size_t row = (size_t)(b * SS + q0 + m0 + r_in + 8 * r);
            const int col = h * HDD + nh * 8 + c_in;
            *(uint32_t*)&yh[row * DD + col] = pack_h(a0, a1);
        }
    }
}

// ---------------------------------------------------------------------------
extern "C" void kernel_launch(void* const* d_in, const int* in_sizes, int n_in,
                              void* d_out, int out_size)
{
    const float* x      = (const float*)d_in[0];
    const float* W_attn = (const float*)d_in[1];
    const float* b_attn = (const float*)d_in[2];
    const float* W_proj = (const float*)d_in[3];
    const float* b_proj = (const float*)d_in[4];
    float* out = (float*)d_out;

    __half *qkv_hi, *qkv_lo, *x_hi, *wa_hi, *wa_lo, *wp_hi, *wp_lo, *y_hi;
    cudaGetSymbolAddress((void**)&qkv_hi, g_qkv_hi);
    cudaGetSymbolAddress((void**)&qkv_lo, g_qkv_lo);
    cudaGetSymbolAddress((void**)&x_hi,  g_x_hi);
    cudaGetSymbolAddress((void**)&wa_hi, g_wa_hi);
    cudaGetSymbolAddress((void**)&wa_lo, g_wa_lo);
    cudaGetSymbolAddress((void**)&wp_hi, g_wp_hi);
    cudaGetSymbolAddress((void**)&wp_lo, g_wp_lo);
    cudaGetSymbolAddress((void**)&y_hi,  g_y_hi);

    cudaFuncSetAttribute(gemm_bias_tc<0>,
                         cudaFuncAttributeMaxDynamicSharedMemorySize, GEMM_SMEM);
    cudaFuncSetAttribute(gemm_bias_tc<1>,
                         cudaFuncAttributeMaxDynamicSharedMemorySize, GEMM_SMEM);
    cudaFuncSetAttribute(flash_attn_tc,
                         cudaFuncAttributeMaxDynamicSharedMemorySize, ATT_SMEM_BYTES);

    // 0) split inputs: x -> hi only; weights -> hi+lo
    {
        int n4 = (M_TOT * DD) / 4;
        split_hi_kernel<<<(n4 + 255) / 256, 256>>>(x, x_hi, n4);
        n4 = (DD * N_QKV) / 4;
        split_hilo_kernel<<<(n4 + 255) / 256, 256>>>(W_attn, wa_hi, wa_lo, n4);
        n4 = (DD * DD) / 4;
        split_hilo_kernel<<<(n4 + 255) / 256, 256>>>(W_proj, wp_hi, wp_lo, n4);
    }

    // 1) QKV projection -> qkv hi/lo
    {
        dim3 grid(N_QKV / 128, M_TOT / 128);
        gemm_bias_tc<1><<<grid, 256, GEMM_SMEM>>>(
            x_hi, wa_hi, wa_lo, b_attn, nullptr, qkv_hi, qkv_lo,
            M_TOT, N_QKV, DD);
    }

    // 2) fp16 tensor-core causal flash attention -> y hi
    {
        dim3 grid(SS / 128, HH, BB);
        flash_attn_tc<<<grid, 256, ATT_SMEM_BYTES>>>(qkv_hi, qkv_lo, y_hi);
    }

    // 3) output projection -> fp32 out
    {
        dim3 grid(DD / 128, M_TOT / 128);
        gemm_bias_tc<0><<<grid, 256, GEMM_SMEM>>>(
            y_hi, wp_hi, wp_lo, b_proj, out, nullptr, nullptr,
            M_TOT, DD, DD);
    }
}